// round 2
// baseline (speedup 1.0000x reference)
#include <cuda_runtime.h>

// Swin attention layer, fused per-window, fp32 SIMT baseline.
// M=32, H=W=64, D=256, 8x8 windows (ws=64 tokens), 8 heads (hd=32), shift=4.

#define IMG_M 32
#define IMG_H 64
#define IMG_W 64
#define DIM   256
#define NHEAD 8
#define HDIM  32
#define NWIN  64     // windows per image (8x8)

#define STRIDE 268   // padded row stride (floats) for token-major smem buffers
#define SSTR   68    // padded row stride for scores

#define SM_A 0
#define SM_K (64*STRIDE)
#define SM_V (2*64*STRIDE)
#define SM_T (3*64*STRIDE)
#define SM_FLOATS (3*64*STRIDE + 64*SSTR)   // 55808 floats = 223232 B

// inter-pass intermediate (static scratch: allocation-free rule)
__device__ float g_y[IMG_M*IMG_H*IMG_W*DIM];

__device__ __forceinline__ int regid(int wh, int ww, int t) {
    int r = t >> 3, c = t & 7;
    int hr = (wh == 7) ? ((r < 4) ? 1 : 2) : 0;
    int wr = (ww == 7) ? ((c < 4) ? 1 : 2) : 0;
    return hr * 3 + wr;
}

// C[64][256] = As[64][256] @ Wg[:, colbase:colbase+256] + bias
// thread tile: 8 rows (ty) x 8 cols (tx: cols {tx*4+j} and {128+tx*4+j})
__device__ __forceinline__ void gemm_64x256(
    const float* __restrict__ As, float* __restrict__ Ts,
    const float* __restrict__ Wg, int ldw, int colbase,
    const float* __restrict__ bias, float acc[8][8], int tid)
{
    const int ty = tid >> 5, tx = tid & 31;
#pragma unroll
    for (int i = 0; i < 8; ++i)
#pragma unroll
        for (int j = 0; j < 8; ++j) acc[i][j] = 0.f;

    for (int k0 = 0; k0 < 256; k0 += 16) {
        // stage W tile [16][256] into Ts (coalesced float4)
#pragma unroll
        for (int s = 0; s < 4; ++s) {
            int f4 = tid + s * 256;           // 0..1023
            int row = f4 >> 6, c4 = f4 & 63;
            *(float4*)(Ts + row * 256 + c4 * 4) =
                *(const float4*)(Wg + (k0 + row) * ldw + colbase + c4 * 4);
        }
        __syncthreads();
#pragma unroll
        for (int kk = 0; kk < 16; kk += 4) {
            float4 a4[8];
#pragma unroll
            for (int i = 0; i < 8; ++i)
                a4[i] = *(const float4*)(As + (ty * 8 + i) * STRIDE + k0 + kk);
#pragma unroll
            for (int u = 0; u < 4; ++u) {
                float4 b0 = *(const float4*)(Ts + (kk + u) * 256 + tx * 4);
                float4 b1 = *(const float4*)(Ts + (kk + u) * 256 + 128 + tx * 4);
#pragma unroll
                for (int i = 0; i < 8; ++i) {
                    float av = (u == 0) ? a4[i].x : (u == 1) ? a4[i].y
                             : (u == 2) ? a4[i].z : a4[i].w;
                    acc[i][0] = fmaf(av, b0.x, acc[i][0]);
                    acc[i][1] = fmaf(av, b0.y, acc[i][1]);
                    acc[i][2] = fmaf(av, b0.z, acc[i][2]);
                    acc[i][3] = fmaf(av, b0.w, acc[i][3]);
                    acc[i][4] = fmaf(av, b1.x, acc[i][4]);
                    acc[i][5] = fmaf(av, b1.y, acc[i][5]);
                    acc[i][6] = fmaf(av, b1.z, acc[i][6]);
                    acc[i][7] = fmaf(av, b1.w, acc[i][7]);
                }
            }
        }
        __syncthreads();
    }
    float4 c0 = *(const float4*)(bias + colbase + tx * 4);
    float4 c1 = *(const float4*)(bias + colbase + 128 + tx * 4);
#pragma unroll
    for (int i = 0; i < 8; ++i) {
        acc[i][0] += c0.x; acc[i][1] += c0.y; acc[i][2] += c0.z; acc[i][3] += c0.w;
        acc[i][4] += c1.x; acc[i][5] += c1.y; acc[i][6] += c1.z; acc[i][7] += c1.w;
    }
}

__global__ __launch_bounds__(256, 1)
void swin_pass_kernel(const float* __restrict__ xin,
                      const float* __restrict__ wqkv,
                      const float* __restrict__ bqkv,
                      const float* __restrict__ wo,
                      const float* __restrict__ bo,
                      float* __restrict__ yout,
                      int shifted)
{
    extern __shared__ float sm[];
    float* A  = sm + SM_A;   // x -> q -> attn_out
    float* Kb = sm + SM_K;
    float* Vb = sm + SM_V;
    float* Ts = sm + SM_T;   // W tiles / scores

    const int tid = threadIdx.x;
    const int blk = blockIdx.x;
    const int m  = blk >> 6;
    const int w  = blk & 63;
    const int wh = w >> 3, ww = w & 7;

    const float* srcimg = shifted ? g_y : xin;
    float*       dstimg = shifted ? yout : g_y;

    // ---- phase 0: gather window (with roll for shifted pass) ----
#pragma unroll
    for (int it = 0; it < 16; ++it) {
        int f4 = tid + it * 256;           // 0..4095
        int t  = f4 >> 6;                  // token 0..63
        int c4 = f4 & 63;                  // float4 within token
        int r = t >> 3, c = t & 7;
        int gh = wh * 8 + r, gw = ww * 8 + c;
        if (shifted) { gh = (gh + 4) & 63; gw = (gw + 4) & 63; }
        float4 val = *(const float4*)(srcimg + ((m * IMG_H + gh) * IMG_W + gw) * DIM + c4 * 4);
        *(float4*)(A + t * STRIDE + c4 * 4) = val;
    }
    __syncthreads();

    const int ty = tid >> 5, tx = tid & 31;
    float acc[8][8];

    // ---- phase 1: QKV projections ----
    // K
    gemm_64x256(A, Ts, wqkv, 3 * DIM, 256, bqkv, acc, tid);
#pragma unroll
    for (int i = 0; i < 8; ++i) {
        *(float4*)(Kb + (ty * 8 + i) * STRIDE + tx * 4) =
            make_float4(acc[i][0], acc[i][1], acc[i][2], acc[i][3]);
        *(float4*)(Kb + (ty * 8 + i) * STRIDE + 128 + tx * 4) =
            make_float4(acc[i][4], acc[i][5], acc[i][6], acc[i][7]);
    }
    // V
    gemm_64x256(A, Ts, wqkv, 3 * DIM, 512, bqkv, acc, tid);
#pragma unroll
    for (int i = 0; i < 8; ++i) {
        *(float4*)(Vb + (ty * 8 + i) * STRIDE + tx * 4) =
            make_float4(acc[i][0], acc[i][1], acc[i][2], acc[i][3]);
        *(float4*)(Vb + (ty * 8 + i) * STRIDE + 128 + tx * 4) =
            make_float4(acc[i][4], acc[i][5], acc[i][6], acc[i][7]);
    }
    // Q (overwrites A; final internal sync of gemm guarantees all A reads done)
    gemm_64x256(A, Ts, wqkv, 3 * DIM, 0, bqkv, acc, tid);
#pragma unroll
    for (int i = 0; i < 8; ++i) {
        *(float4*)(A + (ty * 8 + i) * STRIDE + tx * 4) =
            make_float4(acc[i][0], acc[i][1], acc[i][2], acc[i][3]);
        *(float4*)(A + (ty * 8 + i) * STRIDE + 128 + tx * 4) =
            make_float4(acc[i][4], acc[i][5], acc[i][6], acc[i][7]);
    }
    __syncthreads();

    // ---- phase 2: per-head attention ----
    const float scale = 0.17677669529663687f;  // 1/sqrt(32)
    const int sy = tid >> 4, sx = tid & 15;    // scores: 4x4 per thread
    const int ry = tid >> 3, rx = tid & 7;     // attn@v: 2 rows x 4 cols per thread

    for (int h = 0; h < NHEAD; ++h) {
        // scores = q_h @ k_h^T
        float sacc[4][4];
#pragma unroll
        for (int i = 0; i < 4; ++i)
#pragma unroll
            for (int j = 0; j < 4; ++j) sacc[i][j] = 0.f;
#pragma unroll
        for (int d4 = 0; d4 < 8; ++d4) {
            float4 qa[4], kb[4];
#pragma unroll
            for (int i = 0; i < 4; ++i)
                qa[i] = *(const float4*)(A + (sy * 4 + i) * STRIDE + h * HDIM + d4 * 4);
#pragma unroll
            for (int j = 0; j < 4; ++j)
                kb[j] = *(const float4*)(Kb + (sx * 4 + j) * STRIDE + h * HDIM + d4 * 4);
#pragma unroll
            for (int i = 0; i < 4; ++i)
#pragma unroll
                for (int j = 0; j < 4; ++j) {
                    sacc[i][j] = fmaf(qa[i].x, kb[j].x, sacc[i][j]);
                    sacc[i][j] = fmaf(qa[i].y, kb[j].y, sacc[i][j]);
                    sacc[i][j] = fmaf(qa[i].z, kb[j].z, sacc[i][j]);
                    sacc[i][j] = fmaf(qa[i].w, kb[j].w, sacc[i][j]);
                }
        }
        __syncthreads();   // previous head's reads of Ts (attn weights) are done

        // scale + swin mask, write scores
#pragma unroll
        for (int i = 0; i < 4; ++i) {
            int tiq = sy * 4 + i;
            float4 v;
            v.x = sacc[i][0] * scale; v.y = sacc[i][1] * scale;
            v.z = sacc[i][2] * scale; v.w = sacc[i][3] * scale;
            if (shifted) {
                int ri = regid(wh, ww, tiq);
                if (regid(wh, ww, sx * 4 + 0) != ri) v.x += -1e9f;
                if (regid(wh, ww, sx * 4 + 1) != ri) v.y += -1e9f;
                if (regid(wh, ww, sx * 4 + 2) != ri) v.z += -1e9f;
                if (regid(wh, ww, sx * 4 + 3) != ri) v.w += -1e9f;
            }
            *(float4*)(Ts + tiq * SSTR + sx * 4) = v;
        }
        __syncthreads();

        // softmax: 4 threads per row, 16 cols each; combine via quad shuffles
        {
            int row = tid >> 2, part = tid & 3;
            float* srow = Ts + row * SSTR + part * 16;
            float vals[16];
            float mx = -3.4e38f;
#pragma unroll
            for (int u = 0; u < 16; ++u) { vals[u] = srow[u]; mx = fmaxf(mx, vals[u]); }
            mx = fmaxf(mx, __shfl_xor_sync(0xffffffffu, mx, 1));
            mx = fmaxf(mx, __shfl_xor_sync(0xffffffffu, mx, 2));
            float s = 0.f;
#pragma unroll
            for (int u = 0; u < 16; ++u) { vals[u] = __expf(vals[u] - mx); s += vals[u]; }
            s += __shfl_xor_sync(0xffffffffu, s, 1);
            s += __shfl_xor_sync(0xffffffffu, s, 2);
            float inv = 1.f / s;
#pragma unroll
            for (int u = 0; u < 16; ++u) srow[u] = vals[u] * inv;
        }
        __syncthreads();

        // out_h = attn @ v_h, overwrite A[:, h*32 : h*32+32]
        float oacc[2][4];
#pragma unroll
        for (int i = 0; i < 2; ++i)
#pragma unroll
            for (int jj = 0; jj < 4; ++jj) oacc[i][jj] = 0.f;
#pragma unroll 4
        for (int j = 0; j < 64; ++j) {
            float4 bv = *(const float4*)(Vb + j * STRIDE + h * HDIM + rx * 4);
#pragma unroll
            for (int i = 0; i < 2; ++i) {
                float av = Ts[(ry * 2 + i) * SSTR + j];
                oacc[i][0] = fmaf(av, bv.x, oacc[i][0]);
                oacc[i][1] = fmaf(av, bv.y, oacc[i][1]);
                oacc[i][2] = fmaf(av, bv.z, oacc[i][2]);
                oacc[i][3] = fmaf(av, bv.w, oacc[i][3]);
            }
        }
#pragma unroll
        for (int i = 0; i < 2; ++i)
            *(float4*)(A + (ry * 2 + i) * STRIDE + h * HDIM + rx * 4) =
                make_float4(oacc[i][0], oacc[i][1], oacc[i][2], oacc[i][3]);
    }
    __syncthreads();   // attn_out complete + last head's Ts reads done

    // ---- phase 3: output projection + scatter store ----
    gemm_64x256(A, Ts, wo, DIM, 0, bo, acc, tid);
#pragma unroll
    for (int i = 0; i < 8; ++i) {
        int t = ty * 8 + i;
        int r = t >> 3, c = t & 7;
        int gh = wh * 8 + r, gw = ww * 8 + c;
        if (shifted) { gh = (gh + 4) & 63; gw = (gw + 4) & 63; }
        float* o = dstimg + ((m * IMG_H + gh) * IMG_W + gw) * DIM;
        *(float4*)(o + tx * 4) = make_float4(acc[i][0], acc[i][1], acc[i][2], acc[i][3]);
        *(float4*)(o + 128 + tx * 4) = make_float4(acc[i][4], acc[i][5], acc[i][6], acc[i][7]);
    }
}

extern "C" void kernel_launch(void* const* d_in, const int* in_sizes, int n_in,
                              void* d_out, int out_size) {
    (void)in_sizes; (void)n_in; (void)out_size;
    const float* x    = (const float*)d_in[0];
    const float* wqkv = (const float*)d_in[1];
    const float* bqkv = (const float*)d_in[2];
    const float* wo   = (const float*)d_in[3];
    const float* bo   = (const float*)d_in[4];
    float* out = (float*)d_out;

    cudaFuncSetAttribute(swin_pass_kernel,
                         cudaFuncAttributeMaxDynamicSharedMemorySize, SM_FLOATS * 4);

    dim3 grid(IMG_M * NWIN);
    swin_pass_kernel<<<grid, 256, SM_FLOATS * 4>>>(x, wqkv, bqkv, wo, bo, out, 0);
    swin_pass_kernel<<<grid, 256, SM_FLOATS * 4>>>(x, wqkv, bqkv, wo, bo, out, 1);
}

// round 3
// speedup vs baseline: 1.6231x; 1.6231x over previous
#include <cuda_runtime.h>

// Swin attention layer, fused per-window, fp32 SIMT baseline.
// M=32, H=W=64, D=256, 8x8 windows (ws=64 tokens), 8 heads (hd=32), shift=4.

#define IMG_M 32
#define IMG_H 64
#define IMG_W 64
#define DIM   256
#define NHEAD 8
#define HDIM  32
#define NWIN  64     // windows per image (8x8)

#define STRIDE 268   // padded row stride (floats) for token-major smem buffers
#define SSTR   68    // padded row stride for scores

#define SM_A 0
#define SM_K (64*STRIDE)
#define SM_V (2*64*STRIDE)
#define SM_T (3*64*STRIDE)
#define SM_FLOATS (3*64*STRIDE + 64*SSTR)   // 55808 floats = 223232 B

// inter-pass intermediate (static scratch: allocation-free rule)
__device__ float g_y[IMG_M*IMG_H*IMG_W*DIM];

__device__ __forceinline__ int regid(int wh, int ww, int t) {
    int r = t >> 3, c = t & 7;
    int hr = (wh == 7) ? ((r < 4) ? 1 : 2) : 0;
    int wr = (ww == 7) ? ((c < 4) ? 1 : 2) : 0;
    return hr * 3 + wr;
}

// C[64][256] = As[64][256] @ Wg[:, colbase:colbase+256] + bias
// thread tile: 8 rows (ty) x 8 cols (tx: cols {tx*4+j} and {128+tx*4+j})
__device__ __forceinline__ void gemm_64x256(
    const float* __restrict__ As, float* __restrict__ Ts,
    const float* __restrict__ Wg, int ldw, int colbase,
    const float* __restrict__ bias, float acc[8][8], int tid)
{
    const int ty = tid >> 5, tx = tid & 31;
#pragma unroll
    for (int i = 0; i < 8; ++i)
#pragma unroll
        for (int j = 0; j < 8; ++j) acc[i][j] = 0.f;

    for (int k0 = 0; k0 < 256; k0 += 16) {
        // stage W tile [16][256] into Ts (coalesced float4)
#pragma unroll
        for (int s = 0; s < 4; ++s) {
            int f4 = tid + s * 256;           // 0..1023
            int row = f4 >> 6, c4 = f4 & 63;
            *(float4*)(Ts + row * 256 + c4 * 4) =
                *(const float4*)(Wg + (k0 + row) * ldw + colbase + c4 * 4);
        }
        __syncthreads();
#pragma unroll
        for (int kk = 0; kk < 16; kk += 4) {
            float4 a4[8];
#pragma unroll
            for (int i = 0; i < 8; ++i)
                a4[i] = *(const float4*)(As + (ty * 8 + i) * STRIDE + k0 + kk);
#pragma unroll
            for (int u = 0; u < 4; ++u) {
                float4 b0 = *(const float4*)(Ts + (kk + u) * 256 + tx * 4);
                float4 b1 = *(const float4*)(Ts + (kk + u) * 256 + 128 + tx * 4);
#pragma unroll
                for (int i = 0; i < 8; ++i) {
                    float av = (u == 0) ? a4[i].x : (u == 1) ? a4[i].y
                             : (u == 2) ? a4[i].z : a4[i].w;
                    acc[i][0] = fmaf(av, b0.x, acc[i][0]);
                    acc[i][1] = fmaf(av, b0.y, acc[i][1]);
                    acc[i][2] = fmaf(av, b0.z, acc[i][2]);
                    acc[i][3] = fmaf(av, b0.w, acc[i][3]);
                    acc[i][4] = fmaf(av, b1.x, acc[i][4]);
                    acc[i][5] = fmaf(av, b1.y, acc[i][5]);
                    acc[i][6] = fmaf(av, b1.z, acc[i][6]);
                    acc[i][7] = fmaf(av, b1.w, acc[i][7]);
                }
            }
        }
        __syncthreads();
    }
    float4 c0 = *(const float4*)(bias + colbase + tx * 4);
    float4 c1 = *(const float4*)(bias + colbase + 128 + tx * 4);
#pragma unroll
    for (int i = 0; i < 8; ++i) {
        acc[i][0] += c0.x; acc[i][1] += c0.y; acc[i][2] += c0.z; acc[i][3] += c0.w;
        acc[i][4] += c1.x; acc[i][5] += c1.y; acc[i][6] += c1.z; acc[i][7] += c1.w;
    }
}

__global__ __launch_bounds__(256, 1)
void swin_pass_kernel(const float* __restrict__ xin,
                      const float* __restrict__ wqkv,
                      const float* __restrict__ bqkv,
                      const float* __restrict__ wo,
                      const float* __restrict__ bo,
                      float* __restrict__ yout,
                      int shifted)
{
    extern __shared__ float sm[];
    float* A  = sm + SM_A;   // x -> q -> attn_out
    float* Kb = sm + SM_K;
    float* Vb = sm + SM_V;
    float* Ts = sm + SM_T;   // W tiles / scores

    const int tid = threadIdx.x;
    const int blk = blockIdx.x;
    const int m  = blk >> 6;
    const int w  = blk & 63;
    const int wh = w >> 3, ww = w & 7;

    const float* srcimg = shifted ? g_y : xin;
    float*       dstimg = shifted ? yout : g_y;

    // ---- phase 0: gather window (with roll for shifted pass) ----
#pragma unroll
    for (int it = 0; it < 16; ++it) {
        int f4 = tid + it * 256;           // 0..4095
        int t  = f4 >> 6;                  // token 0..63
        int c4 = f4 & 63;                  // float4 within token
        int r = t >> 3, c = t & 7;
        int gh = wh * 8 + r, gw = ww * 8 + c;
        if (shifted) { gh = (gh + 4) & 63; gw = (gw + 4) & 63; }
        float4 val = *(const float4*)(srcimg + ((m * IMG_H + gh) * IMG_W + gw) * DIM + c4 * 4);
        *(float4*)(A + t * STRIDE + c4 * 4) = val;
    }
    __syncthreads();

    const int ty = tid >> 5, tx = tid & 31;
    float acc[8][8];

    // ---- phase 1: QKV projections ----
    // K
    gemm_64x256(A, Ts, wqkv, 3 * DIM, 256, bqkv, acc, tid);
#pragma unroll
    for (int i = 0; i < 8; ++i) {
        *(float4*)(Kb + (ty * 8 + i) * STRIDE + tx * 4) =
            make_float4(acc[i][0], acc[i][1], acc[i][2], acc[i][3]);
        *(float4*)(Kb + (ty * 8 + i) * STRIDE + 128 + tx * 4) =
            make_float4(acc[i][4], acc[i][5], acc[i][6], acc[i][7]);
    }
    // V
    gemm_64x256(A, Ts, wqkv, 3 * DIM, 512, bqkv, acc, tid);
#pragma unroll
    for (int i = 0; i < 8; ++i) {
        *(float4*)(Vb + (ty * 8 + i) * STRIDE + tx * 4) =
            make_float4(acc[i][0], acc[i][1], acc[i][2], acc[i][3]);
        *(float4*)(Vb + (ty * 8 + i) * STRIDE + 128 + tx * 4) =
            make_float4(acc[i][4], acc[i][5], acc[i][6], acc[i][7]);
    }
    // Q (overwrites A; final internal sync of gemm guarantees all A reads done)
    gemm_64x256(A, Ts, wqkv, 3 * DIM, 0, bqkv, acc, tid);
#pragma unroll
    for (int i = 0; i < 8; ++i) {
        *(float4*)(A + (ty * 8 + i) * STRIDE + tx * 4) =
            make_float4(acc[i][0], acc[i][1], acc[i][2], acc[i][3]);
        *(float4*)(A + (ty * 8 + i) * STRIDE + 128 + tx * 4) =
            make_float4(acc[i][4], acc[i][5], acc[i][6], acc[i][7]);
    }
    __syncthreads();

    // ---- phase 2: per-head attention ----
    const float scale = 0.17677669529663687f;  // 1/sqrt(32)
    const int sy = tid >> 4, sx = tid & 15;    // scores: 4x4 per thread
    const int ry = tid >> 3, rx = tid & 7;     // attn@v: 2 rows x 4 cols per thread

    for (int h = 0; h < NHEAD; ++h) {
        // scores = q_h @ k_h^T
        float sacc[4][4];
#pragma unroll
        for (int i = 0; i < 4; ++i)
#pragma unroll
            for (int j = 0; j < 4; ++j) sacc[i][j] = 0.f;
#pragma unroll
        for (int d4 = 0; d4 < 8; ++d4) {
            float4 qa[4], kb[4];
#pragma unroll
            for (int i = 0; i < 4; ++i)
                qa[i] = *(const float4*)(A + (sy * 4 + i) * STRIDE + h * HDIM + d4 * 4);
#pragma unroll
            for (int j = 0; j < 4; ++j)
                kb[j] = *(const float4*)(Kb + (sx * 4 + j) * STRIDE + h * HDIM + d4 * 4);
#pragma unroll
            for (int i = 0; i < 4; ++i)
#pragma unroll
                for (int j = 0; j < 4; ++j) {
                    sacc[i][j] = fmaf(qa[i].x, kb[j].x, sacc[i][j]);
                    sacc[i][j] = fmaf(qa[i].y, kb[j].y, sacc[i][j]);
                    sacc[i][j] = fmaf(qa[i].z, kb[j].z, sacc[i][j]);
                    sacc[i][j] = fmaf(qa[i].w, kb[j].w, sacc[i][j]);
                }
        }
        __syncthreads();   // previous head's reads of Ts (attn weights) are done

        // scale + swin mask, write scores
#pragma unroll
        for (int i = 0; i < 4; ++i) {
            int tiq = sy * 4 + i;
            float4 v;
            v.x = sacc[i][0] * scale; v.y = sacc[i][1] * scale;
            v.z = sacc[i][2] * scale; v.w = sacc[i][3] * scale;
            if (shifted) {
                int ri = regid(wh, ww, tiq);
                if (regid(wh, ww, sx * 4 + 0) != ri) v.x += -1e9f;
                if (regid(wh, ww, sx * 4 + 1) != ri) v.y += -1e9f;
                if (regid(wh, ww, sx * 4 + 2) != ri) v.z += -1e9f;
                if (regid(wh, ww, sx * 4 + 3) != ri) v.w += -1e9f;
            }
            *(float4*)(Ts + tiq * SSTR + sx * 4) = v;
        }
        __syncthreads();

        // softmax: 4 threads per row, 16 cols each; combine via quad shuffles
        {
            int row = tid >> 2, part = tid & 3;
            float* srow = Ts + row * SSTR + part * 16;
            float vals[16];
            float mx = -3.4e38f;
#pragma unroll
            for (int u = 0; u < 16; ++u) { vals[u] = srow[u]; mx = fmaxf(mx, vals[u]); }
            mx = fmaxf(mx, __shfl_xor_sync(0xffffffffu, mx, 1));
            mx = fmaxf(mx, __shfl_xor_sync(0xffffffffu, mx, 2));
            float s = 0.f;
#pragma unroll
            for (int u = 0; u < 16; ++u) { vals[u] = __expf(vals[u] - mx); s += vals[u]; }
            s += __shfl_xor_sync(0xffffffffu, s, 1);
            s += __shfl_xor_sync(0xffffffffu, s, 2);
            float inv = 1.f / s;
#pragma unroll
            for (int u = 0; u < 16; ++u) srow[u] = vals[u] * inv;
        }
        __syncthreads();

        // out_h = attn @ v_h, overwrite A[:, h*32 : h*32+32]
        float oacc[2][4];
#pragma unroll
        for (int i = 0; i < 2; ++i)
#pragma unroll
            for (int jj = 0; jj < 4; ++jj) oacc[i][jj] = 0.f;
#pragma unroll 4
        for (int j = 0; j < 64; ++j) {
            float4 bv = *(const float4*)(Vb + j * STRIDE + h * HDIM + rx * 4);
#pragma unroll
            for (int i = 0; i < 2; ++i) {
                float av = Ts[(ry * 2 + i) * SSTR + j];
                oacc[i][0] = fmaf(av, bv.x, oacc[i][0]);
                oacc[i][1] = fmaf(av, bv.y, oacc[i][1]);
                oacc[i][2] = fmaf(av, bv.z, oacc[i][2]);
                oacc[i][3] = fmaf(av, bv.w, oacc[i][3]);
            }
        }
#pragma unroll
        for (int i = 0; i < 2; ++i)
            *(float4*)(A + (ry * 2 + i) * STRIDE + h * HDIM + rx * 4) =
                make_float4(oacc[i][0], oacc[i][1], oacc[i][2], oacc[i][3]);
    }
    __syncthreads();   // attn_out complete + last head's Ts reads done

    // ---- phase 3: output projection + scatter store ----
    gemm_64x256(A, Ts, wo, DIM, 0, bo, acc, tid);
#pragma unroll
    for (int i = 0; i < 8; ++i) {
        int t = ty * 8 + i;
        int r = t >> 3, c = t & 7;
        int gh = wh * 8 + r, gw = ww * 8 + c;
        if (shifted) { gh = (gh + 4) & 63; gw = (gw + 4) & 63; }
        float* o = dstimg + ((m * IMG_H + gh) * IMG_W + gw) * DIM;
        *(float4*)(o + tx * 4) = make_float4(acc[i][0], acc[i][1], acc[i][2], acc[i][3]);
        *(float4*)(o + 128 + tx * 4) = make_float4(acc[i][4], acc[i][5], acc[i][6], acc[i][7]);
    }
}

extern "C" void kernel_launch(void* const* d_in, const int* in_sizes, int n_in,
                              void* d_out, int out_size) {
    (void)in_sizes; (void)n_in; (void)out_size;
    const float* x    = (const float*)d_in[0];
    const float* wqkv = (const float*)d_in[1];
    const float* bqkv = (const float*)d_in[2];
    const float* wo   = (const float*)d_in[3];
    const float* bo   = (const float*)d_in[4];
    float* out = (float*)d_out;

    cudaFuncSetAttribute(swin_pass_kernel,
                         cudaFuncAttributeMaxDynamicSharedMemorySize, SM_FLOATS * 4);

    dim3 grid(IMG_M * NWIN);
    swin_pass_kernel<<<grid, 256, SM_FLOATS * 4>>>(x, wqkv, bqkv, wo, bo, out, 0);
    swin_pass_kernel<<<grid, 256, SM_FLOATS * 4>>>(x, wqkv, bqkv, wo, bo, out, 1);
}